// round 9
// baseline (speedup 1.0000x reference)
#include <cuda_runtime.h>
#include <cuda_fp16.h>
#include <cstdint>

#define N_NODES 50000
#define N_EDGES 800000

// ---------------- scratch (no allocations allowed) ----------------
__device__ __align__(16) __half g_h16 [N_NODES * 256];
__device__ __align__(16) __half g_h16b[N_NODES * 256];
__device__ __align__(16) __half g_agg16[N_NODES * 256];
__device__ __align__(16) __half g_w16[327680];
__device__ int g_deg[N_NODES];
__device__ int g_row[N_NODES + 1];
__device__ int g_cur[N_NODES];
__device__ int g_csr[N_EDGES];

// ---------------- fp32 -> fp16 converts ----------------
__global__ void k_cvt(const float* __restrict__ in, __half* __restrict__ out, int n) {
    int i = (blockIdx.x * blockDim.x + threadIdx.x) * 4;
    if (i < n) {
        float4 v = *(const float4*)(in + i);
        __half2 a = __floats2half2_rn(v.x, v.y);
        __half2 b = __floats2half2_rn(v.z, v.w);
        uint2 o;
        o.x = *(uint32_t*)&a;
        o.y = *(uint32_t*)&b;
        *(uint2*)(out + i) = o;
    }
}

__global__ void k_cvt_w(const float* __restrict__ w0, const float* __restrict__ w1,
                        const float* __restrict__ w2, const float* __restrict__ w3,
                        const float* __restrict__ w4, const float* __restrict__ w5) {
    int i = (blockIdx.x * blockDim.x + threadIdx.x) * 4;
    if (i >= 327680) return;
    const float* src;
    int off;
    if (i < 262144) {
        int seg = i >> 16;
        src = (seg == 0) ? w0 : (seg == 1) ? w1 : (seg == 2) ? w2 : w3;
        off = i & 65535;
    } else {
        src = (i < 294912) ? w4 : w5;
        off = (i - 262144) & 32767;
    }
    float4 v = *(const float4*)(src + off);
    __half2 a = __floats2half2_rn(v.x, v.y);
    __half2 b = __floats2half2_rn(v.z, v.w);
    uint2 o;
    o.x = *(uint32_t*)&a;
    o.y = *(uint32_t*)&b;
    *(uint2*)(g_w16 + i) = o;
}

// ---------------- CSR build (int4-vectorized edge reads) ----------------
__global__ void k_count4(const int4* __restrict__ dst4, int e4) {
    int i = blockIdx.x * blockDim.x + threadIdx.x;
    if (i < e4) {
        int4 d = __ldg(&dst4[i]);
        atomicAdd(&g_deg[d.x], 1);
        atomicAdd(&g_deg[d.y], 1);
        atomicAdd(&g_deg[d.z], 1);
        atomicAdd(&g_deg[d.w], 1);
    }
}

// single-block scan (warp shuffles); also writes g_cur = exclusive prefix
__global__ void k_scan(int n) {
    __shared__ int wsum[32];
    __shared__ int carry;
    int lane = threadIdx.x & 31, wid = threadIdx.x >> 5;
    if (threadIdx.x == 0) { carry = 0; g_row[0] = 0; }
    __syncthreads();
    for (int base = 0; base < n; base += 1024) {
        int i = base + threadIdx.x;
        int v = (i < n) ? g_deg[i] : 0;
        int x = v;
#pragma unroll
        for (int o = 1; o < 32; o <<= 1) {
            int t = __shfl_up_sync(0xffffffffu, x, o);
            if (lane >= o) x += t;
        }
        if (lane == 31) wsum[wid] = x;
        __syncthreads();
        if (wid == 0) {
            int w = wsum[lane];
#pragma unroll
            for (int o = 1; o < 32; o <<= 1) {
                int t = __shfl_up_sync(0xffffffffu, w, o);
                if (lane >= o) w += t;
            }
            wsum[lane] = w;
        }
        __syncthreads();
        int incl = x + (wid ? wsum[wid - 1] : 0) + carry;
        if (i < n) {
            g_row[i + 1] = incl;
            g_cur[i] = incl - v;
        }
        __syncthreads();
        if (threadIdx.x == 1023) carry = incl;
        __syncthreads();
    }
}

__global__ void k_fill4(const int4* __restrict__ src4, const int4* __restrict__ dst4,
                        int e4) {
    int i = blockIdx.x * blockDim.x + threadIdx.x;
    if (i < e4) {
        int4 s = __ldg(&src4[i]);
        int4 d = __ldg(&dst4[i]);
        g_csr[atomicAdd(&g_cur[d.x], 1)] = s.x;
        g_csr[atomicAdd(&g_cur[d.y], 1)] = s.y;
        g_csr[atomicAdd(&g_cur[d.z], 1)] = s.z;
        g_csr[atomicAdd(&g_cur[d.w], 1)] = s.w;
    }
}

// ---------------- mean aggregation: one warp per node, uint4 lanes --------
__global__ void k_agg16(const __half* __restrict__ h, __half* __restrict__ agg, int n) {
    int v = (blockIdx.x * blockDim.x + threadIdx.x) >> 5;
    if (v >= n) return;
    int lane = threadIdx.x & 31;
    int s = g_row[v], e = g_row[v + 1];
    const uint4* h8 = (const uint4*)h;   // 8 halves per uint4; 32 lanes * 8 = 256
    float a0 = 0.f, a1 = 0.f, a2 = 0.f, a3 = 0.f;
    float a4 = 0.f, a5 = 0.f, a6 = 0.f, a7 = 0.f;
    int i = s;
    for (; i + 2 <= e; i += 2) {
        int u0 = g_csr[i], u1 = g_csr[i + 1];
        uint4 t0 = __ldg(&h8[u0 * 32 + lane]);
        uint4 t1 = __ldg(&h8[u1 * 32 + lane]);
        float2 p;
        p = __half22float2(*(__half2*)&t0.x); a0 += p.x; a1 += p.y;
        p = __half22float2(*(__half2*)&t0.y); a2 += p.x; a3 += p.y;
        p = __half22float2(*(__half2*)&t0.z); a4 += p.x; a5 += p.y;
        p = __half22float2(*(__half2*)&t0.w); a6 += p.x; a7 += p.y;
        p = __half22float2(*(__half2*)&t1.x); a0 += p.x; a1 += p.y;
        p = __half22float2(*(__half2*)&t1.y); a2 += p.x; a3 += p.y;
        p = __half22float2(*(__half2*)&t1.z); a4 += p.x; a5 += p.y;
        p = __half22float2(*(__half2*)&t1.w); a6 += p.x; a7 += p.y;
    }
    if (i < e) {
        uint4 t0 = __ldg(&h8[g_csr[i] * 32 + lane]);
        float2 p;
        p = __half22float2(*(__half2*)&t0.x); a0 += p.x; a1 += p.y;
        p = __half22float2(*(__half2*)&t0.y); a2 += p.x; a3 += p.y;
        p = __half22float2(*(__half2*)&t0.z); a4 += p.x; a5 += p.y;
        p = __half22float2(*(__half2*)&t0.w); a6 += p.x; a7 += p.y;
    }
    float inv = 1.0f / (float)max(e - s, 1);
    __half2 o0 = __floats2half2_rn(a0 * inv, a1 * inv);
    __half2 o1 = __floats2half2_rn(a2 * inv, a3 * inv);
    __half2 o2 = __floats2half2_rn(a4 * inv, a5 * inv);
    __half2 o3 = __floats2half2_rn(a6 * inv, a7 * inv);
    uint4 o;
    o.x = *(uint32_t*)&o0; o.y = *(uint32_t*)&o1;
    o.z = *(uint32_t*)&o2; o.w = *(uint32_t*)&o3;
    ((uint4*)agg)[v * 32 + lane] = o;
}

// ---------------- fp16 tensor-core dual GEMM (persistent, 3-stage) --------
// out = X1@W1^T + X2@W2^T + b (opt relu). X,W fp16 [*,256]; fp32 accumulate.
// Block 128(M) x 128(N) x 64(K), 8 warps (4M x 2N), warp tile 32x64.
// Persistent CTAs loop over tiles (bx-major: concurrent CTAs share W tile).
// 3-stage cp.async pipeline in dynamic smem (110.6 KB, 2 CTAs/SM).

#define PADK 72   // 64 + 8 halves -> 144B row stride, conflict-free ldmatrix
#define ATILE (128 * PADK)              // halves per stage per operand
#define SMEM_GEMM (6 * ATILE * 2)       // 3 stages x (A+B), bytes = 110592

__device__ __forceinline__ void ldm_x4(uint32_t& r0, uint32_t& r1, uint32_t& r2,
                                       uint32_t& r3, uint32_t addr) {
    asm volatile("ldmatrix.sync.aligned.m8n8.x4.shared.b16 {%0,%1,%2,%3}, [%4];"
                 : "=r"(r0), "=r"(r1), "=r"(r2), "=r"(r3) : "r"(addr));
}

__device__ __forceinline__ void mma16816(float* c, const uint32_t* a, const uint32_t* b) {
    asm volatile(
        "mma.sync.aligned.m16n8k16.row.col.f32.f16.f16.f32 "
        "{%0,%1,%2,%3}, {%4,%5,%6,%7}, {%8,%9}, {%0,%1,%2,%3};"
        : "+f"(c[0]), "+f"(c[1]), "+f"(c[2]), "+f"(c[3])
        : "r"(a[0]), "r"(a[1]), "r"(a[2]), "r"(a[3]), "r"(b[0]), "r"(b[1]));
}

__device__ __forceinline__ void cpa16(uint32_t sdst, const void* gsrc, int sz) {
    asm volatile("cp.async.ca.shared.global [%0], [%1], 16, %2;"
                 :: "r"(sdst), "l"(gsrc), "r"(sz));
}

template <int OUT_HALF>
__global__ __launch_bounds__(256) void k_gemm16(
    const __half* __restrict__ X1, const __half* __restrict__ X2,
    const __half* __restrict__ W1, const __half* __restrict__ W2,
    const float* __restrict__ bias, void* __restrict__ outv,
    int M, int Nout, int relu, int ntiles, int gx)
{
    extern __shared__ __align__(16) __half smem[];
    // layout: A0 | A1 | A2 | B0 | B1 | B2

    int tid = threadIdx.x, lane = tid & 31, warp = tid >> 5;
    int wm = warp >> 1, wn = warp & 1;

    uint32_t sbase = (uint32_t)__cvta_generic_to_shared(smem);
    uint32_t sA[3], sB[3];
#pragma unroll
    for (int s = 0; s < 3; s++) {
        sA[s] = sbase + s * ATILE * 2;
        sB[s] = sbase + (3 + s) * ATILE * 2;
    }

    int g = lane >> 2, cq = lane & 3;
    int j = lane & 7, t = lane >> 3;

    for (int tile = blockIdx.x; tile < ntiles; tile += gridDim.x) {
        int bx = tile % gx, by = tile / gx;
        int bm = bx * 128, bn = by * 128;

        float acc[2][8][4];
#pragma unroll
        for (int mi = 0; mi < 2; mi++)
#pragma unroll
            for (int ni = 0; ni < 8; ni++)
#pragma unroll
                for (int r = 0; r < 4; r++) acc[mi][ni][r] = 0.f;

        // stage load: 128 rows x 128B per operand -> 1024 chunks of 16B, 4/thread
#define ISSUE(st) do {                                                         \
    int p_ = (st) >> 2, kk_ = ((st) & 3) * 64;                                 \
    const __half* X_ = p_ ? X2 : X1;                                           \
    const __half* W_ = p_ ? W2 : W1;                                           \
    uint32_t dA_ = sA[(st) % 3];                                               \
    uint32_t dB_ = sB[(st) % 3];                                               \
    _Pragma("unroll")                                                          \
    for (int q_ = 0; q_ < 4; q_++) {                                           \
        int idx_ = tid + q_ * 256;                                             \
        int row_ = idx_ >> 3, ch_ = idx_ & 7;                                  \
        int grow_ = bm + row_;                                                 \
        int sz_ = (grow_ < M) ? 16 : 0;                                        \
        cpa16(dA_ + (row_ * PADK + ch_ * 8) * 2,                               \
              X_ + (size_t)min(grow_, M - 1) * 256 + kk_ + ch_ * 8, sz_);      \
        cpa16(dB_ + (row_ * PADK + ch_ * 8) * 2,                               \
              W_ + (size_t)(bn + row_) * 256 + kk_ + ch_ * 8, 16);             \
    }                                                                          \
    asm volatile("cp.async.commit_group;");                                    \
} while (0)

        ISSUE(0);
        ISSUE(1);
        ISSUE(2);

        for (int it = 0; it < 8; ++it) {
            if (it < 6)      asm volatile("cp.async.wait_group 2;");
            else if (it == 6) asm volatile("cp.async.wait_group 1;");
            else              asm volatile("cp.async.wait_group 0;");
            __syncthreads();
            uint32_t bA = sA[it % 3];
            uint32_t bB = sB[it % 3];
#pragma unroll
            for (int k16 = 0; k16 < 4; k16++) {
                int kh0 = k16 * 16;
                uint32_t a[2][4];
#pragma unroll
                for (int mi = 0; mi < 2; mi++) {
                    int rowa = wm * 32 + mi * 16 + j + (t & 1) * 8;
                    int cola = kh0 + (t >> 1) * 8;
                    ldm_x4(a[mi][0], a[mi][1], a[mi][2], a[mi][3],
                           bA + (rowa * PADK + cola) * 2);
                }
                uint32_t b[8][2];
#pragma unroll
                for (int q = 0; q < 4; q++) {
                    int rowb = wn * 64 + q * 16 + j + (t >> 1) * 8;
                    int colb = kh0 + (t & 1) * 8;
                    uint32_t r0, r1, r2, r3;
                    ldm_x4(r0, r1, r2, r3, bB + (rowb * PADK + colb) * 2);
                    b[2 * q][0] = r0; b[2 * q][1] = r1;
                    b[2 * q + 1][0] = r2; b[2 * q + 1][1] = r3;
                }
#pragma unroll
                for (int mi = 0; mi < 2; mi++)
#pragma unroll
                    for (int ni = 0; ni < 8; ni++)
                        mma16816(acc[mi][ni], a[mi], b[ni]);
            }
            if (it < 5) {
                __syncthreads();
                ISSUE(it + 3);
            }
        }

        // epilogue
#pragma unroll
        for (int mi = 0; mi < 2; mi++) {
            int r0 = bm + wm * 32 + mi * 16 + g;
            int r1 = r0 + 8;
#pragma unroll
            for (int ni = 0; ni < 8; ni++) {
                int col = bn + wn * 64 + ni * 8 + 2 * cq;
                float bx_ = bias[col], by_ = bias[col + 1];
                float v0 = acc[mi][ni][0] + bx_;
                float v1 = acc[mi][ni][1] + by_;
                float v2 = acc[mi][ni][2] + bx_;
                float v3 = acc[mi][ni][3] + by_;
                if (relu) {
                    v0 = fmaxf(v0, 0.f); v1 = fmaxf(v1, 0.f);
                    v2 = fmaxf(v2, 0.f); v3 = fmaxf(v3, 0.f);
                }
                if (OUT_HALF) {
                    __half* o = (__half*)outv;
                    if (r0 < M) *(__half2*)&o[r0 * Nout + col] = __floats2half2_rn(v0, v1);
                    if (r1 < M) *(__half2*)&o[r1 * Nout + col] = __floats2half2_rn(v2, v3);
                } else {
                    float* o = (float*)outv;
                    if (r0 < M) *(float2*)&o[r0 * Nout + col] = make_float2(v0, v1);
                    if (r1 < M) *(float2*)&o[r1 * Nout + col] = make_float2(v2, v3);
                }
            }
        }
        __syncthreads();   // all reads of smem done before next tile overwrites
#undef ISSUE
    }
}

// ---------------- host ----------------
extern "C" void kernel_launch(void* const* d_in, const int* in_sizes, int n_in,
                              void* d_out, int out_size) {
    const float* x = nullptr;
    const int *src = nullptr, *dstp = nullptr;
    const float* Ws[3] = {0, 0, 0};
    const float* Wn[3] = {0, 0, 0};
    const float* bs[3] = {0, 0, 0};
    int c65536 = 0, c256 = 0, c32768 = 0, c800k = 0;
    for (int i = 0; i < n_in; i++) {
        int sz = in_sizes[i];
        void* p = d_in[i];
        if (sz == 12800000) {
            x = (const float*)p;
        } else if (sz == 800000) {
            if (c800k++ == 0) src = (const int*)p; else dstp = (const int*)p;
        } else if (sz == 65536) {
            int k = c65536++;
            if (k == 0) Ws[0] = (const float*)p;
            else if (k == 1) Wn[0] = (const float*)p;
            else if (k == 2) Ws[1] = (const float*)p;
            else Wn[1] = (const float*)p;
        } else if (sz == 32768) {
            if (c32768++ == 0) Ws[2] = (const float*)p; else Wn[2] = (const float*)p;
        } else if (sz == 256) {
            if (c256++ == 0) bs[0] = (const float*)p; else bs[1] = (const float*)p;
        } else if (sz == 128) {
            bs[2] = (const float*)p;
        }
    }

    __half *h16, *h16b, *agg16, *w16;
    int* degp;
    cudaGetSymbolAddress((void**)&h16,   g_h16);
    cudaGetSymbolAddress((void**)&h16b,  g_h16b);
    cudaGetSymbolAddress((void**)&agg16, g_agg16);
    cudaGetSymbolAddress((void**)&w16,   g_w16);
    cudaGetSymbolAddress((void**)&degp,  g_deg);

    // one-time: side stream/events + smem opt-in + persistent grid size
    static cudaStream_t s2 = nullptr;
    static cudaEvent_t ev0, evS;
    static int pgrid = 296;
    if (!s2) {
        cudaStreamCreateWithFlags(&s2, cudaStreamNonBlocking);
        cudaEventCreateWithFlags(&ev0, cudaEventDisableTiming);
        cudaEventCreateWithFlags(&evS, cudaEventDisableTiming);
        cudaFuncSetAttribute((const void*)k_gemm16<1>,
                             cudaFuncAttributeMaxDynamicSharedMemorySize, SMEM_GEMM);
        cudaFuncSetAttribute((const void*)k_gemm16<0>,
                             cudaFuncAttributeMaxDynamicSharedMemorySize, SMEM_GEMM);
        int dev = 0, nsm = 148;
        cudaGetDevice(&dev);
        cudaDeviceGetAttribute(&nsm, cudaDevAttrMultiProcessorCount, dev);
        pgrid = 2 * nsm;
    }

    const int n = N_NODES, e = N_EDGES;

    // fork: cvt_x on stream0 || CSR chain + weight cvt on s2
    cudaEventRecord(ev0, 0);
    cudaStreamWaitEvent(s2, ev0, 0);

    k_cvt<<<12500, 256>>>(x, h16, n * 256);

    cudaMemsetAsync(degp, 0, n * sizeof(int), s2);
    int e4 = e / 4;   // 800000 % 4 == 0
    k_count4<<<(e4 + 255) / 256, 256, 0, s2>>>((const int4*)dstp, e4);
    k_scan<<<1, 1024, 0, s2>>>(n);
    k_fill4<<<(e4 + 255) / 256, 256, 0, s2>>>((const int4*)src, (const int4*)dstp, e4);
    k_cvt_w<<<320, 256, 0, s2>>>(Ws[0], Wn[0], Ws[1], Wn[1], Ws[2], Wn[2]);
    cudaEventRecord(evS, s2);
    cudaStreamWaitEvent(0, evS, 0);   // join

    int aggGrid = (n * 32 + 255) / 256;   // one warp per node, 8 nodes/block
    int gx = (n + 127) / 128;             // 391
    int nt01 = gx * 2;                    // Nout=256 -> 782 tiles
    int nt2  = gx;                        // Nout=128 -> 391 tiles

    // layer 0: h16 -> h16b
    k_agg16<<<aggGrid, 256>>>(h16, agg16, n);
    k_gemm16<1><<<min(pgrid, nt01), 256, SMEM_GEMM>>>(
        h16, agg16, w16 + 0, w16 + 65536, bs[0], h16b, n, 256, 1, nt01, gx);
    // layer 1: h16b -> h16
    k_agg16<<<aggGrid, 256>>>(h16b, agg16, n);
    k_gemm16<1><<<min(pgrid, nt01), 256, SMEM_GEMM>>>(
        h16b, agg16, w16 + 131072, w16 + 196608, bs[1], h16, n, 256, 1, nt01, gx);
    // layer 2: h16 -> d_out (fp32)
    k_agg16<<<aggGrid, 256>>>(h16, agg16, n);
    k_gemm16<0><<<min(pgrid, nt2), 256, SMEM_GEMM>>>(
        h16, agg16, w16 + 262144, w16 + 294912, bs[2], d_out, n, 128, 0, nt2, gx);
}

// round 10
// speedup vs baseline: 1.1314x; 1.1314x over previous
#include <cuda_runtime.h>
#include <cuda_fp16.h>
#include <cstdint>

#define N_NODES 50000
#define N_EDGES 800000

// ---------------- scratch (no allocations allowed) ----------------
__device__ __align__(16) __half g_h16 [N_NODES * 256];   // layer input A
__device__ __align__(16) __half g_h16b[N_NODES * 256];   // layer input B
__device__ __align__(16) __half g_G   [N_NODES * 512];   // GEMM output [hs|hn]
__device__ __align__(16) __half g_w16[327680];           // stacked [Ws;Wn] per layer
__device__ int g_deg[N_NODES];
__device__ int g_row[N_NODES + 1];
__device__ int g_cur[N_NODES];
__device__ int g_csr[N_EDGES];

// ---------------- fp32 -> fp16 converts ----------------
__global__ void k_cvt(const float* __restrict__ in, __half* __restrict__ out, int n) {
    int i = (blockIdx.x * blockDim.x + threadIdx.x) * 4;
    if (i < n) {
        float4 v = *(const float4*)(in + i);
        __half2 a = __floats2half2_rn(v.x, v.y);
        __half2 b = __floats2half2_rn(v.z, v.w);
        uint2 o;
        o.x = *(uint32_t*)&a;
        o.y = *(uint32_t*)&b;
        *(uint2*)(out + i) = o;
    }
}

// stacked layout: [Ws0;Wn0] @0, [Ws1;Wn1] @131072, [Ws2;Wn2] @262144
__global__ void k_cvt_w(const float* __restrict__ w0, const float* __restrict__ w1,
                        const float* __restrict__ w2, const float* __restrict__ w3,
                        const float* __restrict__ w4, const float* __restrict__ w5) {
    int i = (blockIdx.x * blockDim.x + threadIdx.x) * 4;
    if (i >= 327680) return;
    const float* src;
    int off;
    if (i < 262144) {
        int seg = i >> 16;
        src = (seg == 0) ? w0 : (seg == 1) ? w1 : (seg == 2) ? w2 : w3;
        off = i & 65535;
    } else {
        src = (i < 294912) ? w4 : w5;
        off = (i - 262144) & 32767;
    }
    float4 v = *(const float4*)(src + off);
    __half2 a = __floats2half2_rn(v.x, v.y);
    __half2 b = __floats2half2_rn(v.z, v.w);
    uint2 o;
    o.x = *(uint32_t*)&a;
    o.y = *(uint32_t*)&b;
    *(uint2*)(g_w16 + i) = o;
}

// ---------------- CSR build (int4-vectorized edge reads) ----------------
__global__ void k_count4(const int4* __restrict__ dst4, int e4) {
    int i = blockIdx.x * blockDim.x + threadIdx.x;
    if (i < e4) {
        int4 d = __ldg(&dst4[i]);
        atomicAdd(&g_deg[d.x], 1);
        atomicAdd(&g_deg[d.y], 1);
        atomicAdd(&g_deg[d.z], 1);
        atomicAdd(&g_deg[d.w], 1);
    }
}

__global__ void k_scan(int n) {
    __shared__ int wsum[32];
    __shared__ int carry;
    int lane = threadIdx.x & 31, wid = threadIdx.x >> 5;
    if (threadIdx.x == 0) { carry = 0; g_row[0] = 0; }
    __syncthreads();
    for (int base = 0; base < n; base += 1024) {
        int i = base + threadIdx.x;
        int v = (i < n) ? g_deg[i] : 0;
        int x = v;
#pragma unroll
        for (int o = 1; o < 32; o <<= 1) {
            int t = __shfl_up_sync(0xffffffffu, x, o);
            if (lane >= o) x += t;
        }
        if (lane == 31) wsum[wid] = x;
        __syncthreads();
        if (wid == 0) {
            int w = wsum[lane];
#pragma unroll
            for (int o = 1; o < 32; o <<= 1) {
                int t = __shfl_up_sync(0xffffffffu, w, o);
                if (lane >= o) w += t;
            }
            wsum[lane] = w;
        }
        __syncthreads();
        int incl = x + (wid ? wsum[wid - 1] : 0) + carry;
        if (i < n) {
            g_row[i + 1] = incl;
            g_cur[i] = incl - v;
        }
        __syncthreads();
        if (threadIdx.x == 1023) carry = incl;
        __syncthreads();
    }
}

__global__ void k_fill4(const int4* __restrict__ src4, const int4* __restrict__ dst4,
                        int e4) {
    int i = blockIdx.x * blockDim.x + threadIdx.x;
    if (i < e4) {
        int4 s = __ldg(&src4[i]);
        int4 d = __ldg(&dst4[i]);
        g_csr[atomicAdd(&g_cur[d.x], 1)] = s.x;
        g_csr[atomicAdd(&g_cur[d.y], 1)] = s.y;
        g_csr[atomicAdd(&g_cur[d.z], 1)] = s.z;
        g_csr[atomicAdd(&g_cur[d.w], 1)] = s.w;
    }
}

// ---------------- agg + combine ----------------
// G rows are [hs | hn], width 2F halves. out[v] = act(hs[v] + mean_u(hn[u]) + b).
// One warp per node; lane covers F/32 columns.
template <int F, int OUT_HALF, int RELU>
__global__ void k_aggc(const __half* __restrict__ G, const float* __restrict__ bias,
                       void* __restrict__ outv, int n) {
    int v = (blockIdx.x * blockDim.x + threadIdx.x) >> 5;
    if (v >= n) return;
    int lane = threadIdx.x & 31;
    constexpr int GW = 2 * F;       // G row width in halves
    constexpr int CPL = F / 32;     // columns per lane (8 or 4)
    int s = g_row[v], e = g_row[v + 1];

    float a[CPL];
#pragma unroll
    for (int k = 0; k < CPL; k++) a[k] = 0.f;

    int i = s;
    if constexpr (F == 256) {
        for (; i + 2 <= e; i += 2) {
            const __half* p0 = G + (size_t)g_csr[i]     * GW + F;
            const __half* p1 = G + (size_t)g_csr[i + 1] * GW + F;
            uint4 t0 = __ldg((const uint4*)p0 + lane);
            uint4 t1 = __ldg((const uint4*)p1 + lane);
            float2 q;
            q = __half22float2(*(__half2*)&t0.x); a[0] += q.x; a[1] += q.y;
            q = __half22float2(*(__half2*)&t0.y); a[2] += q.x; a[3] += q.y;
            q = __half22float2(*(__half2*)&t0.z); a[4] += q.x; a[5] += q.y;
            q = __half22float2(*(__half2*)&t0.w); a[6] += q.x; a[7] += q.y;
            q = __half22float2(*(__half2*)&t1.x); a[0] += q.x; a[1] += q.y;
            q = __half22float2(*(__half2*)&t1.y); a[2] += q.x; a[3] += q.y;
            q = __half22float2(*(__half2*)&t1.z); a[4] += q.x; a[5] += q.y;
            q = __half22float2(*(__half2*)&t1.w); a[6] += q.x; a[7] += q.y;
        }
        if (i < e) {
            const __half* p0 = G + (size_t)g_csr[i] * GW + F;
            uint4 t0 = __ldg((const uint4*)p0 + lane);
            float2 q;
            q = __half22float2(*(__half2*)&t0.x); a[0] += q.x; a[1] += q.y;
            q = __half22float2(*(__half2*)&t0.y); a[2] += q.x; a[3] += q.y;
            q = __half22float2(*(__half2*)&t0.z); a[4] += q.x; a[5] += q.y;
            q = __half22float2(*(__half2*)&t0.w); a[6] += q.x; a[7] += q.y;
        }
    } else {
        for (; i + 2 <= e; i += 2) {
            const __half* p0 = G + (size_t)g_csr[i]     * GW + F;
            const __half* p1 = G + (size_t)g_csr[i + 1] * GW + F;
            uint2 t0 = __ldg((const uint2*)p0 + lane);
            uint2 t1 = __ldg((const uint2*)p1 + lane);
            float2 q;
            q = __half22float2(*(__half2*)&t0.x); a[0] += q.x; a[1] += q.y;
            q = __half22float2(*(__half2*)&t0.y); a[2] += q.x; a[3] += q.y;
            q = __half22float2(*(__half2*)&t1.x); a[0] += q.x; a[1] += q.y;
            q = __half22float2(*(__half2*)&t1.y); a[2] += q.x; a[3] += q.y;
        }
        if (i < e) {
            const __half* p0 = G + (size_t)g_csr[i] * GW + F;
            uint2 t0 = __ldg((const uint2*)p0 + lane);
            float2 q;
            q = __half22float2(*(__half2*)&t0.x); a[0] += q.x; a[1] += q.y;
            q = __half22float2(*(__half2*)&t0.y); a[2] += q.x; a[3] += q.y;
        }
    }

    float inv = 1.0f / (float)max(e - s, 1);
    float r[CPL];
    // hs + mean + bias
    if constexpr (F == 256) {
        uint4 hv = __ldg((const uint4*)(G + (size_t)v * GW) + lane);
        float2 q;
        q = __half22float2(*(__half2*)&hv.x); r[0] = q.x; r[1] = q.y;
        q = __half22float2(*(__half2*)&hv.y); r[2] = q.x; r[3] = q.y;
        q = __half22float2(*(__half2*)&hv.z); r[4] = q.x; r[5] = q.y;
        q = __half22float2(*(__half2*)&hv.w); r[6] = q.x; r[7] = q.y;
    } else {
        uint2 hv = __ldg((const uint2*)(G + (size_t)v * GW) + lane);
        float2 q;
        q = __half22float2(*(__half2*)&hv.x); r[0] = q.x; r[1] = q.y;
        q = __half22float2(*(__half2*)&hv.y); r[2] = q.x; r[3] = q.y;
    }
#pragma unroll
    for (int k = 0; k < CPL; k++) {
        r[k] += a[k] * inv + __ldg(&bias[lane * CPL + k]);
        if (RELU) r[k] = fmaxf(r[k], 0.f);
    }

    if (OUT_HALF) {
        __half* o = (__half*)outv + (size_t)v * F + lane * CPL;
        if constexpr (F == 256) {
            __half2 h0 = __floats2half2_rn(r[0], r[1]);
            __half2 h1 = __floats2half2_rn(r[2], r[3]);
            __half2 h2 = __floats2half2_rn(r[4], r[5]);
            __half2 h3 = __floats2half2_rn(r[6], r[7]);
            uint4 pk;
            pk.x = *(uint32_t*)&h0; pk.y = *(uint32_t*)&h1;
            pk.z = *(uint32_t*)&h2; pk.w = *(uint32_t*)&h3;
            *(uint4*)o = pk;
        } else {
            __half2 h0 = __floats2half2_rn(r[0], r[1]);
            __half2 h1 = __floats2half2_rn(r[2], r[3]);
            uint2 pk;
            pk.x = *(uint32_t*)&h0; pk.y = *(uint32_t*)&h1;
            *(uint2*)o = pk;
        }
    } else {
        float* o = (float*)outv + (size_t)v * F + lane * CPL;
#pragma unroll
        for (int k = 0; k < CPL; k += 4)
            *(float4*)(o + k) = make_float4(r[k], r[k + 1], r[k + 2], r[k + 3]);
    }
}

// ---------------- fp16 tensor-core GEMM: G = X @ W^T (no bias/relu) -------
// X fp16 [M,256], W fp16 [Nout,256] (stacked [Ws;Wn]). fp16 out.
// Block 128(M) x 128(N) x 64(K), 8 warps (4M x 2N), 2-stage cp.async,
// dynamic smem 72 KB, K=256 -> 4 k-iterations.

#define PADK 72
#define ATILE (128 * PADK)
#define SMEM_GEMM (4 * ATILE * 2)   // 73728 B

__device__ __forceinline__ void ldm_x4(uint32_t& r0, uint32_t& r1, uint32_t& r2,
                                       uint32_t& r3, uint32_t addr) {
    asm volatile("ldmatrix.sync.aligned.m8n8.x4.shared.b16 {%0,%1,%2,%3}, [%4];"
                 : "=r"(r0), "=r"(r1), "=r"(r2), "=r"(r3) : "r"(addr));
}

__device__ __forceinline__ void mma16816(float* c, const uint32_t* a, const uint32_t* b) {
    asm volatile(
        "mma.sync.aligned.m16n8k16.row.col.f32.f16.f16.f32 "
        "{%0,%1,%2,%3}, {%4,%5,%6,%7}, {%8,%9}, {%0,%1,%2,%3};"
        : "+f"(c[0]), "+f"(c[1]), "+f"(c[2]), "+f"(c[3])
        : "r"(a[0]), "r"(a[1]), "r"(a[2]), "r"(a[3]), "r"(b[0]), "r"(b[1]));
}

__device__ __forceinline__ void cpa16(uint32_t sdst, const void* gsrc, int sz) {
    asm volatile("cp.async.ca.shared.global [%0], [%1], 16, %2;"
                 :: "r"(sdst), "l"(gsrc), "r"(sz));
}

__global__ __launch_bounds__(256) void k_gemm1(
    const __half* __restrict__ X, const __half* __restrict__ W,
    __half* __restrict__ out, int M, int Nout)
{
    extern __shared__ __align__(16) __half smem[];
    int tid = threadIdx.x, lane = tid & 31, warp = tid >> 5;
    int wm = warp >> 1, wn = warp & 1;
    int bm = blockIdx.x * 128, bn = blockIdx.y * 128;

    uint32_t sbase = (uint32_t)__cvta_generic_to_shared(smem);
    uint32_t sA0 = sbase;
    uint32_t sA1 = sbase + ATILE * 2;
    uint32_t sB0 = sbase + 2 * ATILE * 2;
    uint32_t sB1 = sbase + 3 * ATILE * 2;

    float acc[2][8][4];
#pragma unroll
    for (int mi = 0; mi < 2; mi++)
#pragma unroll
        for (int ni = 0; ni < 8; ni++)
#pragma unroll
            for (int r = 0; r < 4; r++) acc[mi][ni][r] = 0.f;

#define ISSUE(st) do {                                                         \
    int kk_ = (st) * 64;                                                       \
    uint32_t dA_ = ((st) & 1) ? sA1 : sA0;                                     \
    uint32_t dB_ = ((st) & 1) ? sB1 : sB0;                                     \
    _Pragma("unroll")                                                          \
    for (int q_ = 0; q_ < 4; q_++) {                                           \
        int idx_ = tid + q_ * 256;                                             \
        int row_ = idx_ >> 3, ch_ = idx_ & 7;                                  \
        int grow_ = bm + row_;                                                 \
        int sz_ = (grow_ < M) ? 16 : 0;                                        \
        cpa16(dA_ + (row_ * PADK + ch_ * 8) * 2,                               \
              X + (size_t)min(grow_, M - 1) * 256 + kk_ + ch_ * 8, sz_);       \
        cpa16(dB_ + (row_ * PADK + ch_ * 8) * 2,                               \
              W + (size_t)(bn + row_) * 256 + kk_ + ch_ * 8, 16);              \
    }                                                                          \
    asm volatile("cp.async.commit_group;");                                    \
} while (0)

    ISSUE(0);
    ISSUE(1);

    int g = lane >> 2, cq = lane & 3;
    int j = lane & 7, t = lane >> 3;

    for (int it = 0; it < 4; ++it) {
        if (it < 3) asm volatile("cp.async.wait_group 1;");
        else        asm volatile("cp.async.wait_group 0;");
        __syncthreads();
        uint32_t bA = (it & 1) ? sA1 : sA0;
        uint32_t bB = (it & 1) ? sB1 : sB0;
#pragma unroll
        for (int k16 = 0; k16 < 4; k16++) {
            int kh0 = k16 * 16;
            uint32_t a[2][4];
#pragma unroll
            for (int mi = 0; mi < 2; mi++) {
                int rowa = wm * 32 + mi * 16 + j + (t & 1) * 8;
                int cola = kh0 + (t >> 1) * 8;
                ldm_x4(a[mi][0], a[mi][1], a[mi][2], a[mi][3],
                       bA + (rowa * PADK + cola) * 2);
            }
            uint32_t b[8][2];
#pragma unroll
            for (int q = 0; q < 4; q++) {
                int rowb = wn * 64 + q * 16 + j + (t >> 1) * 8;
                int colb = kh0 + (t & 1) * 8;
                uint32_t r0, r1, r2, r3;
                ldm_x4(r0, r1, r2, r3, bB + (rowb * PADK + colb) * 2);
                b[2 * q][0] = r0; b[2 * q][1] = r1;
                b[2 * q + 1][0] = r2; b[2 * q + 1][1] = r3;
            }
#pragma unroll
            for (int mi = 0; mi < 2; mi++)
#pragma unroll
                for (int ni = 0; ni < 8; ni++)
                    mma16816(acc[mi][ni], a[mi], b[ni]);
        }
        if (it < 2) {
            __syncthreads();
            ISSUE(it + 2);
        }
    }
#undef ISSUE

    // epilogue: raw fp16, no bias/relu
#pragma unroll
    for (int mi = 0; mi < 2; mi++) {
        int r0 = bm + wm * 32 + mi * 16 + g;
        int r1 = r0 + 8;
#pragma unroll
        for (int ni = 0; ni < 8; ni++) {
            int col = bn + wn * 64 + ni * 8 + 2 * cq;
            if (r0 < M)
                *(__half2*)&out[(size_t)r0 * Nout + col] =
                    __floats2half2_rn(acc[mi][ni][0], acc[mi][ni][1]);
            if (r1 < M)
                *(__half2*)&out[(size_t)r1 * Nout + col] =
                    __floats2half2_rn(acc[mi][ni][2], acc[mi][ni][3]);
        }
    }
}

// ---------------- host ----------------
extern "C" void kernel_launch(void* const* d_in, const int* in_sizes, int n_in,
                              void* d_out, int out_size) {
    const float* x = nullptr;
    const int *src = nullptr, *dstp = nullptr;
    const float* Ws[3] = {0, 0, 0};
    const float* Wn[3] = {0, 0, 0};
    const float* bs[3] = {0, 0, 0};
    int c65536 = 0, c256 = 0, c32768 = 0, c800k = 0;
    for (int i = 0; i < n_in; i++) {
        int sz = in_sizes[i];
        void* p = d_in[i];
        if (sz == 12800000) {
            x = (const float*)p;
        } else if (sz == 800000) {
            if (c800k++ == 0) src = (const int*)p; else dstp = (const int*)p;
        } else if (sz == 65536) {
            int k = c65536++;
            if (k == 0) Ws[0] = (const float*)p;
            else if (k == 1) Wn[0] = (const float*)p;
            else if (k == 2) Ws[1] = (const float*)p;
            else Wn[1] = (const float*)p;
        } else if (sz == 32768) {
            if (c32768++ == 0) Ws[2] = (const float*)p; else Wn[2] = (const float*)p;
        } else if (sz == 256) {
            if (c256++ == 0) bs[0] = (const float*)p; else bs[1] = (const float*)p;
        } else if (sz == 128) {
            bs[2] = (const float*)p;
        }
    }

    __half *h16, *h16b, *G, *w16;
    int* degp;
    cudaGetSymbolAddress((void**)&h16,  g_h16);
    cudaGetSymbolAddress((void**)&h16b, g_h16b);
    cudaGetSymbolAddress((void**)&G,    g_G);
    cudaGetSymbolAddress((void**)&w16,  g_w16);
    cudaGetSymbolAddress((void**)&degp, g_deg);

    static cudaStream_t s2 = nullptr;
    static cudaEvent_t ev0, evS;
    if (!s2) {
        cudaStreamCreateWithFlags(&s2, cudaStreamNonBlocking);
        cudaEventCreateWithFlags(&ev0, cudaEventDisableTiming);
        cudaEventCreateWithFlags(&evS, cudaEventDisableTiming);
        cudaFuncSetAttribute((const void*)k_gemm1,
                             cudaFuncAttributeMaxDynamicSharedMemorySize, SMEM_GEMM);
    }

    const int n = N_NODES, e = N_EDGES;
    int aggGrid = (n * 32 + 255) / 256;
    int gx = (n + 127) / 128;   // 391
    dim3 g512(gx, 4);           // Nout=512
    dim3 g256(gx, 2);           // Nout=256

    // fork: s2 builds CSR while stream0 does cvt + layer-0 GEMM
    cudaEventRecord(ev0, 0);
    cudaStreamWaitEvent(s2, ev0, 0);

    // s2: CSR chain (no dependence on h or weights)
    cudaMemsetAsync(degp, 0, n * sizeof(int), s2);
    int e4 = e / 4;
    k_count4<<<(e4 + 255) / 256, 256, 0, s2>>>((const int4*)dstp, e4);
    k_scan<<<1, 1024, 0, s2>>>(n);
    k_fill4<<<(e4 + 255) / 256, 256, 0, s2>>>((const int4*)src, (const int4*)dstp, e4);
    cudaEventRecord(evS, s2);

    // stream0: converts + layer-0 GEMM (hidden behind CSR build and vice versa)
    k_cvt<<<12500, 256>>>(x, h16, n * 256);
    k_cvt_w<<<320, 256>>>(Ws[0], Wn[0], Ws[1], Wn[1], Ws[2], Wn[2]);
    k_gemm1<<<g512, 256, SMEM_GEMM>>>(h16, w16 + 0, G, n, 512);

    cudaStreamWaitEvent(0, evS, 0);   // join: aggc needs CSR

    // layer 0 combine -> h16b
    k_aggc<256, 1, 1><<<aggGrid, 256>>>(G, bs[0], h16b, n);
    // layer 1
    k_gemm1<<<g512, 256, SMEM_GEMM>>>(h16b, w16 + 131072, G, n, 512);
    k_aggc<256, 1, 1><<<aggGrid, 256>>>(G, bs[1], h16, n);
    // layer 2 (stacked [Ws2;Wn2] -> Nout=256; combine writes fp32, no relu)
    k_gemm1<<<g256, 256, SMEM_GEMM>>>(h16, w16 + 262144, G, n, 256);
    k_aggc<128, 0, 0><<<aggGrid, 256>>>(G, bs[2], d_out, n);
}